// round 3
// baseline (speedup 1.0000x reference)
#include <cuda_runtime.h>
#include <cstdint>

#define IN_F   8192
#define OUT_F  8192
#define THR    50.0f
#define NT     256
#define WARPS  (NT / 32)          // 8 warps per block
#define NV     (IN_F / 4)         // 2048 float4 per row
#define LPW    (NV / 32)          // 64 float4 per lane per row
#define BATCH  8                  // outstanding LDG.128 per lane
#define GRID   592                // 4 CTAs/SM * 148 SMs — exactly one resident wave

__device__ unsigned g_row_ctr;

__global__ void snn_init_ctr() { g_row_ctr = 0u; }

__global__ __launch_bounds__(NT, 4)
void snn_persist_kernel(const float* __restrict__ x,
                        const float* __restrict__ syn,
                        const float* __restrict__ mp,
                        const float* __restrict__ thr,
                        const float* __restrict__ elig,
                        float* __restrict__ out) {
    __shared__ float4 xs4[NV];    // 32 KB: spike input, staged once per CTA

    const int t = threadIdx.x;
    const int l = t & 31;

    // ── Stage x into shared (once per CTA lifetime) ──
    const float4* x4 = reinterpret_cast<const float4*>(x);
    #pragma unroll
    for (int i = 0; i < NV / NT; i++)
        xs4[t + i * NT] = x4[t + i * NT];
    __syncthreads();              // only block barrier; none inside the loop

    float* trace_out = out + 2 * (size_t)OUT_F;

    // ── Persistent loop: each warp steals one row at a time ──
    for (;;) {
        unsigned o = 0;
        if (l == 0) o = atomicAdd(&g_row_ctr, 1u);
        o = __shfl_sync(0xffffffffu, o, 0);
        if (o >= OUT_F) break;

        // Phase 1: masked row-sum over syn[o,:]
        const float4* s4 = reinterpret_cast<const float4*>(syn + (size_t)o * IN_F);
        float acc = 0.0f;
        #pragma unroll
        for (int c = 0; c < LPW; c += BATCH) {
            float4 s[BATCH];
            #pragma unroll
            for (int j = 0; j < BATCH; j++)
                s[j] = __ldcs(&s4[l + (c + j) * 32]);   // front-batched, streaming
            #pragma unroll
            for (int j = 0; j < BATCH; j++) {
                float4 xv = xs4[l + (c + j) * 32];
                acc += (s[j].x > THR ? xv.x : 0.0f)
                     + (s[j].y > THR ? xv.y : 0.0f)
                     + (s[j].z > THR ? xv.z : 0.0f)
                     + (s[j].w > THR ? xv.w : 0.0f);
            }
        }
        #pragma unroll
        for (int off = 16; off > 0; off >>= 1)
            acc += __shfl_down_sync(0xffffffffu, acc, off);

        float sp = 0.0f;
        if (l == 0) {
            float v = mp[o] * 0.6f + acc;
            sp = (v >= thr[o]) ? 1.0f : 0.0f;
            out[o] = sp;                                    // spikes
            out[OUT_F + o] = v * (1.0f - sp) * 0.3f;        // v_new
        }
        sp = __shfl_sync(0xffffffffu, sp, 0);

        // Phase 2: trace_new[o,:] = clip(elig*0.7 + sp*x, 0, 3)
        const float4* e4 = reinterpret_cast<const float4*>(elig + (size_t)o * IN_F);
        float4* o4 = reinterpret_cast<float4*>(trace_out + (size_t)o * IN_F);
        #pragma unroll
        for (int c = 0; c < LPW; c += BATCH) {
            float4 e[BATCH];
            #pragma unroll
            for (int j = 0; j < BATCH; j++)
                e[j] = __ldcs(&e4[l + (c + j) * 32]);       // streaming
            #pragma unroll
            for (int j = 0; j < BATCH; j++) {
                float4 xv = xs4[l + (c + j) * 32];
                float4 r;
                r.x = fminf(fmaxf(fmaf(e[j].x, 0.7f, sp * xv.x), 0.0f), 3.0f);
                r.y = fminf(fmaxf(fmaf(e[j].y, 0.7f, sp * xv.y), 0.0f), 3.0f);
                r.z = fminf(fmaxf(fmaf(e[j].z, 0.7f, sp * xv.z), 0.0f), 3.0f);
                r.w = fminf(fmaxf(fmaf(e[j].w, 0.7f, sp * xv.w), 0.0f), 3.0f);
                __stcs(&o4[l + (c + j) * 32], r);           // streaming store
            }
        }
    }
}

extern "C" void kernel_launch(void* const* d_in, const int* in_sizes, int n_in,
                              void* d_out, int out_size) {
    const float* x    = (const float*)d_in[0];  // spike_input [1, 8192]
    const float* syn  = (const float*)d_in[1];  // synapse_states [8192, 8192]
    const float* mp   = (const float*)d_in[2];  // membrane_potential [8192]
    const float* thr  = (const float*)d_in[3];  // adaptive_threshold [8192]
    const float* elig = (const float*)d_in[4];  // eligibility_trace [8192, 8192]
    float* out = (float*)d_out;                 // [spikes | v_new | trace_new]

    snn_init_ctr<<<1, 1>>>();                   // reset work counter (graph-safe)
    snn_persist_kernel<<<GRID, NT>>>(x, syn, mp, thr, elig, out);
}

// round 4
// speedup vs baseline: 1.4849x; 1.4849x over previous
#include <cuda_runtime.h>
#include <cstdint>

#define IN_F   8192
#define OUT_F  8192
#define THR    50.0f
#define NT     256
#define WARPS  (NT / 32)          // 8 warps per block, one row per warp
#define NV     (IN_F / 4)         // 2048 float4 per row
#define LPW    (NV / 32)          // 64 float4 per lane per row
#define BATCH  4                  // outstanding LDG.128 per lane (reg-lean)

__global__ __launch_bounds__(NT)
void snn_warp2_kernel(const float* __restrict__ x,
                      const float* __restrict__ syn,
                      const float* __restrict__ mp,
                      const float* __restrict__ thr,
                      const float* __restrict__ elig,
                      float* __restrict__ out) {
    const int t = threadIdx.x;
    const int w = t >> 5;
    const int l = t & 31;
    const int o = blockIdx.x * WARPS + w;

    const float4* x4 = reinterpret_cast<const float4*>(x);  // 32 KB, L1-resident

    // ── Phase 1: current = sum_i x[i] * (syn[o,i] > 50) ──
    const float4* s4 = reinterpret_cast<const float4*>(syn + (size_t)o * IN_F) + l;
    float acc = 0.0f;
    #pragma unroll
    for (int c = 0; c < LPW; c += BATCH) {
        float4 s[BATCH];
        #pragma unroll
        for (int j = 0; j < BATCH; j++)
            s[j] = __ldcs(s4 + (c + j) * 32);               // streaming, front-batched
        #pragma unroll
        for (int j = 0; j < BATCH; j++) {
            float4 xv = __ldg(x4 + l + (c + j) * 32);       // L1 hit
            acc += (s[j].x > THR ? xv.x : 0.0f)
                 + (s[j].y > THR ? xv.y : 0.0f)
                 + (s[j].z > THR ? xv.z : 0.0f)
                 + (s[j].w > THR ? xv.w : 0.0f);
        }
    }
    #pragma unroll
    for (int off = 16; off > 0; off >>= 1)
        acc += __shfl_down_sync(0xffffffffu, acc, off);

    float sp = 0.0f;
    if (l == 0) {
        float v = __ldg(mp + o) * 0.6f + acc;
        sp = (v >= __ldg(thr + o)) ? 1.0f : 0.0f;
        out[o] = sp;                                        // spikes
        out[OUT_F + o] = v * (1.0f - sp) * 0.3f;            // v_new
    }
    sp = __shfl_sync(0xffffffffu, sp, 0);

    // ── Phase 2: trace_new = clip(elig*0.7 + sp*x, 0, 3) ──
    const float4* e4 = reinterpret_cast<const float4*>(elig + (size_t)o * IN_F) + l;
    float4* o4 = reinterpret_cast<float4*>(out + 2 * (size_t)OUT_F
                                               + (size_t)o * IN_F) + l;
    #pragma unroll
    for (int c = 0; c < LPW; c += BATCH) {
        float4 e[BATCH];
        #pragma unroll
        for (int j = 0; j < BATCH; j++)
            e[j] = __ldcs(e4 + (c + j) * 32);               // streaming
        #pragma unroll
        for (int j = 0; j < BATCH; j++) {
            float4 xv = __ldg(x4 + l + (c + j) * 32);       // L1 hit
            float4 r;
            r.x = fminf(fmaxf(fmaf(e[j].x, 0.7f, sp * xv.x), 0.0f), 3.0f);
            r.y = fminf(fmaxf(fmaf(e[j].y, 0.7f, sp * xv.y), 0.0f), 3.0f);
            r.z = fminf(fmaxf(fmaf(e[j].z, 0.7f, sp * xv.z), 0.0f), 3.0f);
            r.w = fminf(fmaxf(fmaf(e[j].w, 0.7f, sp * xv.w), 0.0f), 3.0f);
            __stcs(o4 + (c + j) * 32, r);                   // streaming store
        }
    }
}

extern "C" void kernel_launch(void* const* d_in, const int* in_sizes, int n_in,
                              void* d_out, int out_size) {
    const float* x    = (const float*)d_in[0];  // spike_input [1, 8192]
    const float* syn  = (const float*)d_in[1];  // synapse_states [8192, 8192]
    const float* mp   = (const float*)d_in[2];  // membrane_potential [8192]
    const float* thr  = (const float*)d_in[3];  // adaptive_threshold [8192]
    const float* elig = (const float*)d_in[4];  // eligibility_trace [8192, 8192]
    float* out = (float*)d_out;                 // [spikes | v_new | trace_new]

    snn_warp2_kernel<<<OUT_F / WARPS, NT>>>(x, syn, mp, thr, elig, out);
}

// round 5
// speedup vs baseline: 1.9138x; 1.2888x over previous
#include <cuda_runtime.h>
#include <cstdint>

#define IN_F   8192
#define OUT_F  8192
#define THR    50.0f
#define NT     256
#define NV     (IN_F / 4)         // 2048 float4 per row
#define FPT    (NV / NT)          // 8 float4 per thread — one burst covers the row

// ── Kernel A: spikes + v_new (reads syn, 256 MB) ──
__global__ __launch_bounds__(NT)
void snn_spike_kernel(const float* __restrict__ x,
                      const float* __restrict__ syn,
                      const float* __restrict__ mp,
                      const float* __restrict__ thr,
                      float* __restrict__ out) {
    __shared__ float red[NT / 32];
    const int o = blockIdx.x;
    const int t = threadIdx.x;

    const float4* s4 = reinterpret_cast<const float4*>(syn + (size_t)o * IN_F);
    const float4* x4 = reinterpret_cast<const float4*>(x);

    // One front-batched burst of 8 LDG.128 — full row, max MLP
    float4 s[FPT];
    #pragma unroll
    for (int j = 0; j < FPT; j++)
        s[j] = __ldcs(&s4[t + j * NT]);

    float acc = 0.0f;
    #pragma unroll
    for (int j = 0; j < FPT; j++) {
        float4 xv = __ldg(&x4[t + j * NT]);      // 32 KB, L1-resident
        acc += (s[j].x > THR ? xv.x : 0.0f)
             + (s[j].y > THR ? xv.y : 0.0f)
             + (s[j].z > THR ? xv.z : 0.0f)
             + (s[j].w > THR ? xv.w : 0.0f);
    }
    #pragma unroll
    for (int off = 16; off > 0; off >>= 1)
        acc += __shfl_down_sync(0xffffffffu, acc, off);
    if ((t & 31) == 0) red[t >> 5] = acc;
    __syncthreads();

    if (t == 0) {
        float cur = 0.0f;
        #pragma unroll
        for (int w = 0; w < NT / 32; w++) cur += red[w];
        float v  = __ldg(mp + o) * 0.6f + cur;
        float sp = (v >= __ldg(thr + o)) ? 1.0f : 0.0f;
        out[o] = sp;                                   // spikes
        out[OUT_F + o] = v * (1.0f - sp) * 0.3f;       // v_new
    }
}

// ── Kernel B: trace update (reads elig 256 MB, writes trace 256 MB) ──
__global__ __launch_bounds__(NT)
void snn_trace_kernel(const float* __restrict__ x,
                      const float* __restrict__ elig,
                      const float* __restrict__ spikes,  // = out[0..OUT_F)
                      float* __restrict__ trace) {       // = out + 2*OUT_F
    const int o = blockIdx.x;
    const int t = threadIdx.x;

    const float sp = __ldg(&spikes[o]);          // uniform per block, L1 broadcast

    const float4* e4 = reinterpret_cast<const float4*>(elig + (size_t)o * IN_F);
    const float4* x4 = reinterpret_cast<const float4*>(x);
    float4* o4 = reinterpret_cast<float4*>(trace + (size_t)o * IN_F);

    float4 e[FPT];
    #pragma unroll
    for (int j = 0; j < FPT; j++)
        e[j] = __ldcs(&e4[t + j * NT]);          // one 8-deep burst

    #pragma unroll
    for (int j = 0; j < FPT; j++) {
        float4 xv = __ldg(&x4[t + j * NT]);      // L1 hit
        float4 r;
        r.x = fminf(fmaxf(fmaf(e[j].x, 0.7f, sp * xv.x), 0.0f), 3.0f);
        r.y = fminf(fmaxf(fmaf(e[j].y, 0.7f, sp * xv.y), 0.0f), 3.0f);
        r.z = fminf(fmaxf(fmaf(e[j].z, 0.7f, sp * xv.z), 0.0f), 3.0f);
        r.w = fminf(fmaxf(fmaf(e[j].w, 0.7f, sp * xv.w), 0.0f), 3.0f);
        __stcs(&o4[t + j * NT], r);              // streaming store
    }
}

extern "C" void kernel_launch(void* const* d_in, const int* in_sizes, int n_in,
                              void* d_out, int out_size) {
    const float* x    = (const float*)d_in[0];  // spike_input [1, 8192]
    const float* syn  = (const float*)d_in[1];  // synapse_states [8192, 8192]
    const float* mp   = (const float*)d_in[2];  // membrane_potential [8192]
    const float* thr  = (const float*)d_in[3];  // adaptive_threshold [8192]
    const float* elig = (const float*)d_in[4];  // eligibility_trace [8192, 8192]
    float* out = (float*)d_out;                 // [spikes | v_new | trace_new]

    snn_spike_kernel<<<OUT_F, NT>>>(x, syn, mp, thr, out);
    snn_trace_kernel<<<OUT_F, NT>>>(x, elig, out, out + 2 * (size_t)OUT_F);
}